// round 5
// baseline (speedup 1.0000x reference)
#include <cuda_runtime.h>
#include <cstdint>

// Problem constants
#define M_TOK 16384     // 4 * 64 * 64 tokens
#define KDIM  2944      // padded in_features (2880 real + 64 zero)
#define KREAL 2880
#define ODIM  384
#define RANKD 32

// ---------------- device scratch (no cudaMalloc allowed) ----------------
__device__ __align__(16) int8_t g_qx[(size_t)M_TOK * KDIM];   // ~48 MB
__device__ __align__(16) int8_t g_qw[(size_t)ODIM * KDIM];    // ~1.1 MB
__device__ float g_sx[M_TOK];
__device__ float g_sw[ODIM];
__device__ __align__(16) float g_r[(size_t)M_TOK * RANKD];    // 2 MB

// ---------------- helpers ----------------
__device__ __forceinline__ void fma2(unsigned long long& acc,
                                     unsigned long long a,
                                     unsigned long long b) {
    asm("fma.rn.f32x2 %0, %1, %2, %0;" : "+l"(acc) : "l"(a), "l"(b));
}

__device__ __forceinline__ void load9(const float* __restrict__ xc,
                                      int ho, int wo, float v[9]) {
#pragma unroll
    for (int i = 0; i < 3; i++) {
        int h = ho + i - 1;
        bool hok = ((unsigned)h < 64u);
#pragma unroll
        for (int j = 0; j < 3; j++) {
            int wc = wo + j - 1;
            v[i * 3 + j] = (hok && ((unsigned)wc < 64u))
                               ? __ldg(xc + h * 64 + wc) : 0.0f;
        }
    }
}

// ---------------- kernel 1: per-out-channel int4 weight quant ----------------
__global__ void __launch_bounds__(256) quant_w_kernel(const float* __restrict__ w) {
    int warp = (blockIdx.x * blockDim.x + threadIdx.x) >> 5;
    int lane = threadIdx.x & 31;
    if (warp >= ODIM) return;
    const float* row = w + (size_t)warp * KDIM;
    float amax = 0.0f;
    for (int k = lane; k < KDIM; k += 32) amax = fmaxf(amax, fabsf(row[k]));
#pragma unroll
    for (int off = 16; off; off >>= 1)
        amax = fmaxf(amax, __shfl_xor_sync(0xFFFFFFFFu, amax, off));
    float s = fmaxf(__fdiv_rn(amax, 7.0f), 1e-8f);
    if (lane == 0) g_sw[warp] = s;
    int8_t* q = g_qw + (size_t)warp * KDIM;
    for (int k = lane; k < KDIM; k += 32) {
        float t = __fdiv_rn(row[k], s);            // IEEE div: match jnp round ties
        float r = fminf(fmaxf(rintf(t), -8.0f), 7.0f);
        q[k] = (int8_t)(int)r;
    }
}

// ---------------- kernel 2: im2col + amax + int4 act quant + LoRA-down ----------------
// One lane per token; warp covers 32 consecutive wo. Pass 1 computes amax and
// r = xu . proj_down (packed f32x2 FMAs). Pass 2 recomputes the im2col values
// (L2-resident) and writes packed int8 qx row-major.
__global__ void __launch_bounds__(256) im2col_quant_kernel(
    const float* __restrict__ x, const float* __restrict__ pd) {
    int wid  = (blockIdx.x * 256 + threadIdx.x) >> 5;   // 0..511
    int lane = threadIdx.x & 31;
    int n    = wid >> 7;            // 4 images
    int rem  = wid & 127;           // 2 warps per row * 64 rows
    int ho   = rem >> 1;
    int wo   = ((rem & 1) << 5) + lane;
    int t    = n * 4096 + ho * 64 + wo;

    const float* xb = x + (size_t)n * 320 * 4096;

    unsigned long long acc2[16];
#pragma unroll
    for (int q = 0; q < 16; q++) acc2[q] = 0ULL;
    float amax = 0.0f;

    for (int c = 0; c < 320; c++) {
        const float* xc = xb + (size_t)c * 4096;
        float v[9];
        load9(xc, ho, wo, v);
        const ulonglong2* pdrow =
            reinterpret_cast<const ulonglong2*>(pd + (size_t)(c * 9) * 32);
#pragma unroll
        for (int tp = 0; tp < 9; tp++) {
            float val = v[tp];
            amax = fmaxf(amax, fabsf(val));
            unsigned vb = __float_as_uint(val);
            unsigned long long v2;
            asm("mov.b64 %0, {%1, %1};" : "=l"(v2) : "r"(vb));
            const ulonglong2* prow = pdrow + tp * 8;   // 16 ull = 8 ull2 per row
#pragma unroll
            for (int q = 0; q < 8; q++) {
                ulonglong2 p = __ldg(prow + q);
                fma2(acc2[2 * q],     v2, p.x);
                fma2(acc2[2 * q + 1], v2, p.y);
            }
        }
    }

    float s = fmaxf(__fdiv_rn(amax, 7.0f), 1e-8f);
    g_sx[t] = s;

    // store LoRA-down result
    float* rout = g_r + (size_t)t * RANKD;
#pragma unroll
    for (int q = 0; q < 16; q++) {
        unsigned lo, hi;
        asm("mov.b64 {%0, %1}, %2;" : "=r"(lo), "=r"(hi) : "l"(acc2[q]));
        rout[2 * q]     = __uint_as_float(lo);
        rout[2 * q + 1] = __uint_as_float(hi);
    }

    // pass 2: quantize + pack
    int8_t* qrow = g_qx + (size_t)t * KDIM;
    unsigned word = 0;
    int nb = 0, kout = 0;
    for (int c = 0; c < 320; c++) {
        const float* xc = xb + (size_t)c * 4096;
        float v[9];
        load9(xc, ho, wo, v);
#pragma unroll
        for (int tp = 0; tp < 9; tp++) {
            float tq = __fdiv_rn(v[tp], s);         // IEEE div
            float r  = fminf(fmaxf(rintf(tq), -8.0f), 7.0f);
            int iq   = (int)r;
            word |= ((unsigned)(iq & 0xFF)) << (nb * 8);
            if (++nb == 4) {
                *reinterpret_cast<unsigned*>(qrow + kout) = word;
                kout += 4; word = 0; nb = 0;
            }
        }
    }
    // zero pad region [2880, 2944)
#pragma unroll
    for (int k = KREAL; k < KDIM; k += 4)
        *reinterpret_cast<unsigned*>(qrow + k) = 0u;
}

// ---------------- kernel 3: dp4a int GEMM + fused LoRA-up/bias epilogue ----------------
// Tile 128x128, BK=32 bytes. acc = qx . qw (int32); out = acc*sx*sw + r.proj_up + bias.
struct SmMM { int As[8][128]; int Bs[8][128]; };
struct SmEP { float Rt[128 * 32]; float PU[32 * 128];
              float sxs[128]; float sws[128]; float bs[128]; };
union SmU { SmMM mm; SmEP ep; };

__global__ void __launch_bounds__(256, 2) gemm_kernel(
    const float* __restrict__ proj_up, const float* __restrict__ bias,
    float* __restrict__ out) {
    __shared__ SmU sm;

    int bx = blockIdx.x;
    int mt = bx & 127;          // 128 m-tiles
    int nt = bx >> 7;           // 3 n-tiles
    int m0 = mt << 7, n0 = nt << 7;
    int tid = threadIdx.x;
    int tx = tid & 15, ty = tid >> 4;

    int acc[8][8];
#pragma unroll
    for (int i = 0; i < 8; i++)
#pragma unroll
        for (int j = 0; j < 8; j++) acc[i][j] = 0;

    const int8_t* Abase = g_qx + (size_t)m0 * KDIM;
    const int8_t* Bbase = g_qw + (size_t)n0 * KDIM;

    for (int k0 = 0; k0 < KDIM; k0 += 32) {
#pragma unroll
        for (int rr = 0; rr < 4; rr++) {
            int id = tid + (rr << 8);
            int m = id >> 3, w = id & 7;
            sm.mm.As[w][m] = *reinterpret_cast<const int*>(
                Abase + (size_t)m * KDIM + k0 + (w << 2));
            sm.mm.Bs[w][m] = *reinterpret_cast<const int*>(
                Bbase + (size_t)m * KDIM + k0 + (w << 2));
        }
        __syncthreads();
#pragma unroll
        for (int w = 0; w < 8; w++) {
            int a[8], b[8];
            *reinterpret_cast<int4*>(a)     = *reinterpret_cast<const int4*>(&sm.mm.As[w][ty << 3]);
            *reinterpret_cast<int4*>(a + 4) = *reinterpret_cast<const int4*>(&sm.mm.As[w][(ty << 3) + 4]);
            *reinterpret_cast<int4*>(b)     = *reinterpret_cast<const int4*>(&sm.mm.Bs[w][tx << 3]);
            *reinterpret_cast<int4*>(b + 4) = *reinterpret_cast<const int4*>(&sm.mm.Bs[w][(tx << 3) + 4]);
#pragma unroll
            for (int i = 0; i < 8; i++)
#pragma unroll
                for (int j = 0; j < 8; j++)
                    acc[i][j] = __dp4a(a[i], b[j], acc[i][j]);
        }
        __syncthreads();
    }

    // ---- epilogue: repurpose smem ----
#pragma unroll
    for (int rr = 0; rr < 16; rr++) {
        int id = tid + (rr << 8);                    // 0..4095
        sm.ep.Rt[id] = g_r[(size_t)m0 * RANKD + id]; // [m][rank], contiguous
        sm.ep.PU[id] = proj_up[(id >> 7) * ODIM + n0 + (id & 127)];
    }
    if (tid < 128) {
        sm.ep.sxs[tid] = g_sx[m0 + tid];
        sm.ep.sws[tid] = g_sw[n0 + tid];
        sm.ep.bs[tid]  = bias[n0 + tid];
    }
    __syncthreads();

    // convert int acc -> float with scales + bias first (frees int regs)
    float facc[8][8];
#pragma unroll
    for (int i = 0; i < 8; i++) {
        float sxm = sm.ep.sxs[(ty << 3) + i];
#pragma unroll
        for (int j = 0; j < 8; j++) {
            int nn = (tx << 3) + j;
            facc[i][j] = (float)acc[i][j] * sxm * sm.ep.sws[nn] + sm.ep.bs[nn];
        }
    }
    // + LoRA-up: facc += Rt[m][:] . PU[:][n]
#pragma unroll
    for (int rr = 0; rr < 32; rr++) {
        float av[8], bv[8];
#pragma unroll
        for (int i = 0; i < 8; i++)
            av[i] = sm.ep.Rt[((ty << 3) + i) * 32 + rr];
        *reinterpret_cast<float4*>(bv)     = *reinterpret_cast<const float4*>(&sm.ep.PU[rr * 128 + (tx << 3)]);
        *reinterpret_cast<float4*>(bv + 4) = *reinterpret_cast<const float4*>(&sm.ep.PU[rr * 128 + (tx << 3) + 4]);
#pragma unroll
        for (int i = 0; i < 8; i++)
#pragma unroll
            for (int j = 0; j < 8; j++)
                facc[i][j] += av[i] * bv[j];
    }

#pragma unroll
    for (int i = 0; i < 8; i++) {
        int m = (ty << 3) + i;
        float* orow = out + (size_t)(m0 + m) * ODIM + n0 + (tx << 3);
        *reinterpret_cast<float4*>(orow)     = *reinterpret_cast<float4*>(&facc[i][0]);
        *reinterpret_cast<float4*>(orow + 4) = *reinterpret_cast<float4*>(&facc[i][4]);
    }
}

// ---------------- launch ----------------
extern "C" void kernel_launch(void* const* d_in, const int* in_sizes, int n_in,
                              void* d_out, int out_size) {
    const float* x    = (const float*)d_in[0];  // (4,320,64,64)
    const float* w    = (const float*)d_in[1];  // (384,2944)
    const float* pd   = (const float*)d_in[2];  // (2944,32)
    const float* pu   = (const float*)d_in[3];  // (32,384)
    const float* bias = (const float*)d_in[4];  // (384,)
    float* out = (float*)d_out;                 // (4,4096,384) fp32

    quant_w_kernel<<<48, 256>>>(w);            // 384 warps, one per out-channel
    im2col_quant_kernel<<<64, 256>>>(x, pd);   // 512 warps, 32 tokens each
    gemm_kernel<<<384, 256>>>(pu, bias, out);  // 128 m-tiles x 3 n-tiles
}

// round 7
// speedup vs baseline: 3.6532x; 3.6532x over previous
#include <cuda_runtime.h>
#include <cstdint>

// Problem constants
#define M_TOK 16384     // 4 * 64 * 64 tokens
#define KDIM  2944      // padded in_features (2880 real + 64 zero)
#define KREAL 2880
#define ODIM  384
#define RANKD 32

#define CH_P  40        // channels per chunk in partial (amax+LoRA-down) kernel
#define NCH_P 8
#define CH_Q  64        // channels per chunk in quantize kernel
#define NCH_Q 5

// ---------------- device scratch (no cudaMalloc allowed) ----------------
__device__ __align__(16) int8_t g_qx[(size_t)M_TOK * KDIM];    // ~48 MB
__device__ __align__(16) int8_t g_qw[(size_t)ODIM * KDIM];     // ~1.1 MB
__device__ float g_sx[M_TOK];
__device__ float g_sw[ODIM];
__device__ __align__(16) float g_r[(size_t)M_TOK * RANKD];     // 2 MB
__device__ __align__(16) float g_rp[NCH_P][M_TOK][RANKD];      // 16.8 MB partial LoRA-down
__device__ float g_amp[NCH_P][M_TOK];                          // partial amax

// ---------------- helpers ----------------
__device__ __forceinline__ void fma2(unsigned long long& acc,
                                     unsigned long long a,
                                     unsigned long long b) {
    asm("fma.rn.f32x2 %0, %1, %2, %0;" : "+l"(acc) : "l"(a), "l"(b));
}

__device__ __forceinline__ void load9(const float* __restrict__ xc,
                                      int ho, int wo, float v[9]) {
#pragma unroll
    for (int i = 0; i < 3; i++) {
        int h = ho + i - 1;
        bool hok = ((unsigned)h < 64u);
#pragma unroll
        for (int j = 0; j < 3; j++) {
            int wc = wo + j - 1;
            v[i * 3 + j] = (hok && ((unsigned)wc < 64u))
                               ? __ldg(xc + h * 64 + wc) : 0.0f;
        }
    }
}

// ---------------- kernel 1: per-out-channel int4 weight quant ----------------
__global__ void __launch_bounds__(256) quant_w_kernel(const float* __restrict__ w) {
    int warp = (blockIdx.x * blockDim.x + threadIdx.x) >> 5;
    int lane = threadIdx.x & 31;
    if (warp >= ODIM) return;
    const float* row = w + (size_t)warp * KDIM;
    float amax = 0.0f;
    for (int k = lane; k < KDIM; k += 32) amax = fmaxf(amax, fabsf(row[k]));
#pragma unroll
    for (int off = 16; off; off >>= 1)
        amax = fmaxf(amax, __shfl_xor_sync(0xFFFFFFFFu, amax, off));
    float s = fmaxf(__fdiv_rn(amax, 7.0f), 1e-8f);
    if (lane == 0) g_sw[warp] = s;
    int8_t* q = g_qw + (size_t)warp * KDIM;
    for (int k = lane; k < KDIM; k += 32) {
        float t = __fdiv_rn(row[k], s);            // IEEE div: match jnp round ties
        float r = fminf(fmaxf(rintf(t), -8.0f), 7.0f);
        q[k] = (int8_t)(int)r;
    }
}

// ---------------- kernel 2a: partial amax + partial LoRA-down per channel chunk -----
// grid (64 token-blocks, 8 channel-chunks), 256 threads, 1 token/thread.
// proj_down chunk staged in smem (45 KB); packed f32x2 FMA accumulation.
__global__ void __launch_bounds__(256) im2col_partial_kernel(
    const float* __restrict__ x, const float* __restrict__ pd) {
    __shared__ float spd[CH_P * 9 * 32];            // 46080 B
    int chunk = blockIdx.y;
    int tid = threadIdx.x;

    // stage proj_down rows [chunk*360, chunk*360+360) into smem (float4)
    const float4* src = reinterpret_cast<const float4*>(pd + (size_t)chunk * CH_P * 9 * 32);
    float4* dst = reinterpret_cast<float4*>(spd);
#pragma unroll 4
    for (int i = tid; i < CH_P * 9 * 8; i += 256) dst[i] = __ldg(src + i);
    __syncthreads();

    int t  = blockIdx.x * 256 + tid;
    int wo = t & 63, ho = (t >> 6) & 63, n = t >> 12;
    const float* xb = x + ((size_t)n * 320 + chunk * CH_P) * 4096;

    unsigned long long acc2[16];
#pragma unroll
    for (int q = 0; q < 16; q++) acc2[q] = 0ULL;
    float amax = 0.0f;

    for (int c = 0; c < CH_P; c++) {
        const float* xc = xb + (size_t)c * 4096;
        float v[9];
        load9(xc, ho, wo, v);
        const ulonglong2* base =
            reinterpret_cast<const ulonglong2*>(spd + c * 9 * 32);
#pragma unroll
        for (int tp = 0; tp < 9; tp++) {
            float val = v[tp];
            amax = fmaxf(amax, fabsf(val));
            unsigned vb = __float_as_uint(val);
            unsigned long long v2;
            asm("mov.b64 %0, {%1, %1};" : "=l"(v2) : "r"(vb));
            const ulonglong2* prow = base + tp * 8;   // 32 floats = 8 ull2
#pragma unroll
            for (int q = 0; q < 8; q++) {
                ulonglong2 p = prow[q];
                fma2(acc2[2 * q],     v2, p.x);
                fma2(acc2[2 * q + 1], v2, p.y);
            }
        }
    }

    g_amp[chunk][t] = amax;
    unsigned long long* rout =
        reinterpret_cast<unsigned long long*>(&g_rp[chunk][t][0]);
#pragma unroll
    for (int q = 0; q < 16; q++) rout[q] = acc2[q];
}

// ---------------- kernel 2b: deterministic reduction of partials ----------------
__global__ void __launch_bounds__(256) reduce_kernel() {
    int idx = blockIdx.x * 256 + threadIdx.x;    // 0 .. 16384*32
    int t = idx >> 5, r = idx & 31;
    float s = 0.0f;
#pragma unroll
    for (int ch = 0; ch < NCH_P; ch++) s += g_rp[ch][t][r];
    g_r[(size_t)t * RANKD + r] = s;
    if (r == 0) {
        float am = 0.0f;
#pragma unroll
        for (int ch = 0; ch < NCH_P; ch++) am = fmaxf(am, g_amp[ch][t]);
        g_sx[t] = fmaxf(__fdiv_rn(am, 7.0f), 1e-8f);
    }
}

// ---------------- kernel 2c: quantize + pack (parallel over token x chunk) -------
__global__ void __launch_bounds__(256) quant_x_kernel(const float* __restrict__ x) {
    int chunk = blockIdx.y;
    int tid = threadIdx.x;
    int t  = blockIdx.x * 256 + tid;
    int wo = t & 63, ho = (t >> 6) & 63, n = t >> 12;
    float s = g_sx[t];
    const float* xb = x + ((size_t)n * 320 + chunk * CH_Q) * 4096;
    int8_t* qrow = g_qx + (size_t)t * KDIM + chunk * CH_Q * 9;

    unsigned word = 0;
    int nb = 0, kout = 0;
    for (int c = 0; c < CH_Q; c++) {
        const float* xc = xb + (size_t)c * 4096;
        float v[9];
        load9(xc, ho, wo, v);
#pragma unroll
        for (int tp = 0; tp < 9; tp++) {
            float tq = __fdiv_rn(v[tp], s);         // IEEE div
            float r  = fminf(fmaxf(rintf(tq), -8.0f), 7.0f);
            int iq   = (int)r;
            word |= ((unsigned)(iq & 0xFF)) << (nb * 8);
            if (++nb == 4) {
                *reinterpret_cast<unsigned*>(qrow + kout) = word;
                kout += 4; word = 0; nb = 0;
            }
        }
    }
    // zero pad region [2880, 2944) once
    if (chunk == NCH_Q - 1) {
        int4 z = make_int4(0, 0, 0, 0);
        int4* pz = reinterpret_cast<int4*>(g_qx + (size_t)t * KDIM + KREAL);
#pragma unroll
        for (int k = 0; k < 4; k++) pz[k] = z;
    }
}

// ---------------- kernel 3: dp4a int GEMM + fused LoRA-up/bias epilogue ----------
// Tile 128x96, BK=32 bytes, 512 blocks, 3 CTAs/SM. Smem k-major-transposed with
// stride 132 (conflict-free STS and LDS).
#define LDT 132
struct SmMM { int As[8][LDT]; int Bs[8][LDT]; };
struct SmEP { float Rt[128 * 32]; float PU[32 * 96];
              float sxs[128]; float sws[96]; float bs[96]; };
union SmU { SmMM mm; SmEP ep; };

__global__ void __launch_bounds__(256, 3) gemm_kernel(
    const float* __restrict__ proj_up, const float* __restrict__ bias,
    float* __restrict__ out) {
    __shared__ SmU sm;

    int bx = blockIdx.x;
    int mt = bx >> 2;           // 128 m-tiles
    int nt = bx & 3;            // 4 n-tiles of 96
    int m0 = mt << 7, n0 = nt * 96;
    int tid = threadIdx.x;
    int tx = tid & 15, ty = tid >> 4;        // tx: 6 n each, ty: 8 m each

    int acc[8][6];
#pragma unroll
    for (int i = 0; i < 8; i++)
#pragma unroll
        for (int j = 0; j < 6; j++) acc[i][j] = 0;

    const int8_t* Abase = g_qx + (size_t)m0 * KDIM;
    const int8_t* Bbase = g_qw + (size_t)n0 * KDIM;

    for (int k0 = 0; k0 < KDIM; k0 += 32) {
        // A: 128 rows x 8 ints
#pragma unroll
        for (int rr = 0; rr < 4; rr++) {
            int id = tid + (rr << 8);
            int m = id >> 3, w = id & 7;
            sm.mm.As[w][m] = *reinterpret_cast<const int*>(
                Abase + (size_t)m * KDIM + k0 + (w << 2));
        }
        // B: 96 rows x 8 ints
#pragma unroll
        for (int rr = 0; rr < 3; rr++) {
            int id = tid + (rr << 8);
            int nn = id >> 3, w = id & 7;
            sm.mm.Bs[w][nn] = *reinterpret_cast<const int*>(
                Bbase + (size_t)nn * KDIM + k0 + (w << 2));
        }
        __syncthreads();
#pragma unroll
        for (int w = 0; w < 8; w++) {
            int a[8], b[6];
            *reinterpret_cast<int4*>(a)     = *reinterpret_cast<const int4*>(&sm.mm.As[w][ty << 3]);
            *reinterpret_cast<int4*>(a + 4) = *reinterpret_cast<const int4*>(&sm.mm.As[w][(ty << 3) + 4]);
            *reinterpret_cast<int2*>(b)     = *reinterpret_cast<const int2*>(&sm.mm.Bs[w][tx * 6]);
            *reinterpret_cast<int2*>(b + 2) = *reinterpret_cast<const int2*>(&sm.mm.Bs[w][tx * 6 + 2]);
            *reinterpret_cast<int2*>(b + 4) = *reinterpret_cast<const int2*>(&sm.mm.Bs[w][tx * 6 + 4]);
#pragma unroll
            for (int i = 0; i < 8; i++)
#pragma unroll
                for (int j = 0; j < 6; j++)
                    acc[i][j] = __dp4a(a[i], b[j], acc[i][j]);
        }
        __syncthreads();
    }

    // ---- epilogue: repurpose smem ----
#pragma unroll
    for (int rr = 0; rr < 16; rr++) {
        int id = tid + (rr << 8);                    // 0..4095
        sm.ep.Rt[id] = g_r[(size_t)m0 * RANKD + id]; // [m][rank]
    }
#pragma unroll
    for (int rr = 0; rr < 12; rr++) {
        int id = tid + (rr << 8);                    // 0..3071
        sm.ep.PU[id] = proj_up[(id / 96) * ODIM + n0 + (id % 96)];
    }
    if (tid < 128) sm.ep.sxs[tid] = g_sx[m0 + tid];
    if (tid < 96) {
        sm.ep.sws[tid] = g_sw[n0 + tid];
        sm.ep.bs[tid]  = bias[n0 + tid];
    }
    __syncthreads();

    float facc[8][6];
#pragma unroll
    for (int i = 0; i < 8; i++) {
        float sxm = sm.ep.sxs[(ty << 3) + i];
#pragma unroll
        for (int j = 0; j < 6; j++) {
            int nn = tx * 6 + j;
            facc[i][j] = (float)acc[i][j] * sxm * sm.ep.sws[nn] + sm.ep.bs[nn];
        }
    }
    // + LoRA-up: facc += Rt[m][:] . PU[:][n]
#pragma unroll
    for (int rr = 0; rr < 32; rr++) {
        float av[8], bv[6];
#pragma unroll
        for (int i = 0; i < 8; i++)
            av[i] = sm.ep.Rt[((ty << 3) + i) * 32 + rr];
        *reinterpret_cast<float2*>(bv)     = *reinterpret_cast<const float2*>(&sm.ep.PU[rr * 96 + tx * 6]);
        *reinterpret_cast<float2*>(bv + 2) = *reinterpret_cast<const float2*>(&sm.ep.PU[rr * 96 + tx * 6 + 2]);
        *reinterpret_cast<float2*>(bv + 4) = *reinterpret_cast<const float2*>(&sm.ep.PU[rr * 96 + tx * 6 + 4]);
#pragma unroll
        for (int i = 0; i < 8; i++)
#pragma unroll
            for (int j = 0; j < 6; j++)
                facc[i][j] += av[i] * bv[j];
    }

#pragma unroll
    for (int i = 0; i < 8; i++) {
        int m = (ty << 3) + i;
        float* orow = out + (size_t)(m0 + m) * ODIM + n0 + tx * 6;
        *reinterpret_cast<float2*>(orow)     = *reinterpret_cast<float2*>(&facc[i][0]);
        *reinterpret_cast<float2*>(orow + 2) = *reinterpret_cast<float2*>(&facc[i][2]);
        *reinterpret_cast<float2*>(orow + 4) = *reinterpret_cast<float2*>(&facc[i][4]);
    }
}

// ---------------- launch ----------------
extern "C" void kernel_launch(void* const* d_in, const int* in_sizes, int n_in,
                              void* d_out, int out_size) {
    const float* x    = (const float*)d_in[0];  // (4,320,64,64)
    const float* w    = (const float*)d_in[1];  // (384,2944)
    const float* pd   = (const float*)d_in[2];  // (2944,32)
    const float* pu   = (const float*)d_in[3];  // (32,384)
    const float* bias = (const float*)d_in[4];  // (384,)
    float* out = (float*)d_out;                 // (4,4096,384) fp32

    quant_w_kernel<<<48, 256>>>(w);                         // 384 warps
    im2col_partial_kernel<<<dim3(64, NCH_P), 256>>>(x, pd); // 512 blocks
    reduce_kernel<<<(M_TOK * RANKD) / 256, 256>>>();        // 2048 blocks
    quant_x_kernel<<<dim3(64, NCH_Q), 256>>>(x);            // 320 blocks
    gemm_kernel<<<512, 256>>>(pu, bias, out);               // 128 m x 4 n tiles
}

// round 13
// speedup vs baseline: 4.0885x; 1.1192x over previous
#include <cuda_runtime.h>
#include <cstdint>

// Problem constants
#define M_TOK 16384     // 4 * 64 * 64 tokens
#define KDIM  2944      // padded in_features (2880 real + 64 zero)
#define KREAL 2880
#define ODIM  384
#define RANKD 32

#define CH_P  40        // channels per chunk in partial (amax+LoRA-down) kernel
#define NCH_P 8
#define CH_Q  32        // channels per chunk in quantize kernel
#define NCH_Q 10

#define NKC   (KDIM / 16)   // 184 k-chunks of 16 bytes
#define NST   (KDIM / 64)   // 46 GEMM k-stages of 64 bytes
#define STAGE_BYTES 10240   // 128 rows * 80B padded stride

// ---------------- device scratch (no cudaMalloc allowed) ----------------
// qx layout: [k-chunk (184)][token (16384)] x 16 bytes  -> coalesced writes+reads
__device__ __align__(16) int8_t g_qx[(size_t)NKC * M_TOK * 16];   // 48 MB
__device__ __align__(16) int8_t g_qw[(size_t)ODIM * KDIM];        // 1.1 MB row-major
__device__ float g_sx[M_TOK];
__device__ float g_sw[ODIM];
__device__ __align__(16) float g_r[(size_t)M_TOK * RANKD];        // 2 MB
__device__ __align__(16) float g_rp[NCH_P][M_TOK][RANKD];         // 16.8 MB
__device__ float g_amp[NCH_P][M_TOK];
__device__ __align__(16) float g_yl[(size_t)M_TOK * ODIM];        // 25 MB (lora+bias)

// ---------------- PTX helpers (baseline compute_103 only!) ----------------
__device__ __forceinline__ uint32_t smem_u32(const void* p) {
    uint32_t a;
    asm("{ .reg .u64 t; cvta.to.shared.u64 t, %1; cvt.u32.u64 %0, t; }"
        : "=r"(a) : "l"(p));
    return a;
}
__device__ __forceinline__ void cp16(uint32_t s, const void* g) {
    asm volatile("cp.async.cg.shared.global [%0], [%1], 16;" :: "r"(s), "l"(g));
}
#define CP_COMMIT() asm volatile("cp.async.commit_group;" ::: "memory")
#define CP_WAIT(n)  asm volatile("cp.async.wait_group %0;" :: "n"(n) : "memory")

__device__ __forceinline__ void mma_s8(int* c, const int* a, const int* b) {
    asm volatile(
        "mma.sync.aligned.m16n8k32.row.col.s32.s8.s8.s32 "
        "{%0,%1,%2,%3}, {%4,%5,%6,%7}, {%8,%9}, {%0,%1,%2,%3};"
        : "+r"(c[0]), "+r"(c[1]), "+r"(c[2]), "+r"(c[3])
        : "r"(a[0]), "r"(a[1]), "r"(a[2]), "r"(a[3]), "r"(b[0]), "r"(b[1]));
}

// ---------------- math helpers ----------------
__device__ __forceinline__ void fma2(unsigned long long& acc,
                                     unsigned long long a,
                                     unsigned long long b) {
    asm("fma.rn.f32x2 %0, %1, %2, %0;" : "+l"(acc) : "l"(a), "l"(b));
}
__device__ __forceinline__ void load9(const float* __restrict__ xc,
                                      int ho, int wo, float v[9]) {
#pragma unroll
    for (int i = 0; i < 3; i++) {
        int h = ho + i - 1;
        bool hok = ((unsigned)h < 64u);
#pragma unroll
        for (int j = 0; j < 3; j++) {
            int wc = wo + j - 1;
            v[i * 3 + j] = (hok && ((unsigned)wc < 64u))
                               ? __ldg(xc + h * 64 + wc) : 0.0f;
        }
    }
}

// ---------------- kernel 1: per-out-channel int4 weight quant ----------------
__global__ void __launch_bounds__(256) quant_w_kernel(const float* __restrict__ w) {
    int warp = (blockIdx.x * blockDim.x + threadIdx.x) >> 5;
    int lane = threadIdx.x & 31;
    if (warp >= ODIM) return;
    const float* row = w + (size_t)warp * KDIM;
    float amax = 0.0f;
    for (int k = lane; k < KDIM; k += 32) amax = fmaxf(amax, fabsf(row[k]));
#pragma unroll
    for (int off = 16; off; off >>= 1)
        amax = fmaxf(amax, __shfl_xor_sync(0xFFFFFFFFu, amax, off));
    float s = fmaxf(__fdiv_rn(amax, 7.0f), 1e-8f);
    if (lane == 0) g_sw[warp] = s;
    int8_t* q = g_qw + (size_t)warp * KDIM;
    for (int k = lane; k < KDIM; k += 32) {
        float t = __fdiv_rn(row[k], s);            // IEEE div: match jnp round ties
        float r = fminf(fmaxf(rintf(t), -8.0f), 7.0f);
        q[k] = (int8_t)(int)r;
    }
}

// ---------------- kernel 2a: partial amax + partial LoRA-down ----------------
__global__ void __launch_bounds__(256) im2col_partial_kernel(
    const float* __restrict__ x, const float* __restrict__ pd) {
    __shared__ float spd[CH_P * 9 * 32];            // 46080 B
    int chunk = blockIdx.y;
    int tid = threadIdx.x;

    const float4* src = reinterpret_cast<const float4*>(pd + (size_t)chunk * CH_P * 9 * 32);
    float4* dst = reinterpret_cast<float4*>(spd);
#pragma unroll 4
    for (int i = tid; i < CH_P * 9 * 8; i += 256) dst[i] = __ldg(src + i);
    __syncthreads();

    int t  = blockIdx.x * 256 + tid;
    int wo = t & 63, ho = (t >> 6) & 63, n = t >> 12;
    const float* xb = x + ((size_t)n * 320 + chunk * CH_P) * 4096;

    unsigned long long acc2[16];
#pragma unroll
    for (int q = 0; q < 16; q++) acc2[q] = 0ULL;
    float amax = 0.0f;

    for (int c = 0; c < CH_P; c++) {
        const float* xc = xb + (size_t)c * 4096;
        float v[9];
        load9(xc, ho, wo, v);
        const ulonglong2* base =
            reinterpret_cast<const ulonglong2*>(spd + c * 9 * 32);
#pragma unroll
        for (int tp = 0; tp < 9; tp++) {
            float val = v[tp];
            amax = fmaxf(amax, fabsf(val));
            unsigned vb = __float_as_uint(val);
            unsigned long long v2;
            asm("mov.b64 %0, {%1, %1};" : "=l"(v2) : "r"(vb));
            const ulonglong2* prow = base + tp * 8;
#pragma unroll
            for (int q = 0; q < 8; q++) {
                ulonglong2 p = prow[q];
                fma2(acc2[2 * q],     v2, p.x);
                fma2(acc2[2 * q + 1], v2, p.y);
            }
        }
    }

    g_amp[chunk][t] = amax;
    unsigned long long* rout =
        reinterpret_cast<unsigned long long*>(&g_rp[chunk][t][0]);
#pragma unroll
    for (int q = 0; q < 16; q++) rout[q] = acc2[q];
}

// ---------------- kernel 2b: deterministic reduction ----------------
__global__ void __launch_bounds__(256) reduce_kernel() {
    int idx = blockIdx.x * 256 + threadIdx.x;
    int t = idx >> 5, r = idx & 31;
    float s = 0.0f;
#pragma unroll
    for (int ch = 0; ch < NCH_P; ch++) s += g_rp[ch][t][r];
    g_r[(size_t)t * RANKD + r] = s;
    if (r == 0) {
        float am = 0.0f;
#pragma unroll
        for (int ch = 0; ch < NCH_P; ch++) am = fmaxf(am, g_amp[ch][t]);
        g_sx[t] = fmaxf(__fdiv_rn(am, 7.0f), 1e-8f);
    }
}

// ---------------- kernel 2c: LoRA-up + bias -> g_yl ----------------
// One warp per token; PU (32x384) staged in smem; rv broadcast via shuffle.
__global__ void __launch_bounds__(256) lora_up_kernel(
    const float* __restrict__ pu, const float* __restrict__ bias) {
    __shared__ float sPU[RANKD * ODIM];             // 49152 B
    int tid = threadIdx.x, wid = tid >> 5, lane = tid & 31;
#pragma unroll 4
    for (int i = tid; i < RANKD * ODIM / 4; i += 256)
        reinterpret_cast<float4*>(sPU)[i] =
            __ldg(reinterpret_cast<const float4*>(pu) + i);
    __syncthreads();

    int t = blockIdx.x * 8 + wid;
    float rvl = g_r[(size_t)t * RANKD + lane];
    float acc[12];
#pragma unroll
    for (int j = 0; j < 12; j++) acc[j] = __ldg(bias + lane + 32 * j);
#pragma unroll
    for (int r = 0; r < RANKD; r++) {
        float rb = __shfl_sync(0xFFFFFFFFu, rvl, r);
        const float* prow = sPU + r * ODIM + lane;
#pragma unroll
        for (int j = 0; j < 12; j++) acc[j] = fmaf(rb, prow[32 * j], acc[j]);
    }
    float* yrow = g_yl + (size_t)t * ODIM + lane;
#pragma unroll
    for (int j = 0; j < 12; j++) yrow[32 * j] = acc[j];
}

// ---------------- kernel 2d: quantize + pack int8, chunked-k layout ----------
__global__ void __launch_bounds__(256) quant_x_kernel(const float* __restrict__ x) {
    int chunk = blockIdx.y;
    int tid = threadIdx.x;
    int t  = blockIdx.x * 256 + tid;
    int wo = t & 63, ho = (t >> 6) & 63, n = t >> 12;
    float s = g_sx[t];
    const float* xb = x + ((size_t)n * 320 + chunk * CH_Q) * 4096;

#pragma unroll
    for (int grp = 0; grp < 2; grp++) {            // 16 channels -> 144 B -> 9 chunks
        unsigned hw[36];
#pragma unroll
        for (int i = 0; i < 36; i++) hw[i] = 0u;
#pragma unroll
        for (int c16 = 0; c16 < 16; c16++) {
            const float* xc = xb + (size_t)(grp * 16 + c16) * 4096;
            float v[9];
            load9(xc, ho, wo, v);
#pragma unroll
            for (int tp = 0; tp < 9; tp++) {
                float tq = __fdiv_rn(v[tp], s);     // IEEE div
                float r  = fminf(fmaxf(rintf(tq), -8.0f), 7.0f);
                int iq   = (int)r;
                int idx  = c16 * 9 + tp;
                hw[idx >> 2] |= ((unsigned)(iq & 0xFF)) << ((idx & 3) * 8);
            }
        }
        int kc0 = chunk * 18 + grp * 9;
#pragma unroll
        for (int j = 0; j < 9; j++) {
            uint4 w4 = make_uint4(hw[4 * j], hw[4 * j + 1], hw[4 * j + 2], hw[4 * j + 3]);
            *reinterpret_cast<uint4*>(
                g_qx + ((size_t)(kc0 + j) * M_TOK + t) * 16) = w4;
        }
    }
    // zero pad chunks 180..183 (k bytes 2880..2944)
    if (chunk == NCH_Q - 1) {
        uint4 z = make_uint4(0, 0, 0, 0);
#pragma unroll
        for (int kc = 180; kc < 184; kc++)
            *reinterpret_cast<uint4*>(g_qx + ((size_t)kc * M_TOK + t) * 16) = z;
    }
}

// ---------------- kernel 3: IMMA (mma.sync s8) GEMM + epilogue ----------------
// Block 128x128, 8 warps in 2(m)x4(n), warp tile 64x32. k-stage = 64 bytes,
// double-buffered cp.async. smem row stride 80B -> conflict-free fragment LDS.
__global__ void __launch_bounds__(256, 2) mma_gemm_kernel(float* __restrict__ out) {
    __shared__ int8_t sA[2 * STAGE_BYTES];
    __shared__ int8_t sB[2 * STAGE_BYTES];

    int tid = threadIdx.x, wid = tid >> 5, lane = tid & 31;
    int g = lane >> 2, q = lane & 3;
    int mt = blockIdx.x / 3, nt = blockIdx.x - mt * 3;
    int m0 = mt << 7, n0 = nt << 7;
    int wm0 = (wid >> 2) << 6;      // 0 or 64
    int wn0 = (wid & 3) << 5;       // 0,32,64,96

    uint32_t sAb = smem_u32(sA), sBb = smem_u32(sB);

    auto issue = [&](int st, int kt) {
#pragma unroll
        for (int rep = 0; rep < 2; rep++) {
            int c = tid + (rep << 8);
            int seg = c >> 7, row = c & 127;
            cp16(sAb + st * STAGE_BYTES + row * 80 + seg * 16,
                 g_qx + ((size_t)(kt * 4 + seg) * M_TOK + m0 + row) * 16);
            cp16(sBb + st * STAGE_BYTES + row * 80 + seg * 16,
                 g_qw + (size_t)(n0 + row) * KDIM + kt * 64 + seg * 16);
        }
        CP_COMMIT();
    };

    int acc[4][4][4];
#pragma unroll
    for (int mi = 0; mi < 4; mi++)
#pragma unroll
        for (int ni = 0; ni < 4; ni++)
#pragma unroll
            for (int r = 0; r < 4; r++) acc[mi][ni][r] = 0;

    issue(0, 0);

    for (int kt = 0; kt < NST; kt++) {
        int st = kt & 1;
        if (kt + 1 < NST) { issue(st ^ 1, kt + 1); CP_WAIT(1); }
        else               { CP_WAIT(0); }
        __syncthreads();

        const int8_t* Ab = sA + st * STAGE_BYTES;
        const int8_t* Bb = sB + st * STAGE_BYTES;
#pragma unroll
        for (int ks = 0; ks < 2; ks++) {
            int a[4][4], b[4][2];
#pragma unroll
            for (int mi = 0; mi < 4; mi++) {
                const int8_t* p = Ab + (wm0 + mi * 16 + g) * 80 + ks * 32 + q * 4;
                a[mi][0] = *reinterpret_cast<const int*>(p);
                a[mi][1] = *reinterpret_cast<const int*>(p + 8 * 80);
                a[mi][2] = *reinterpret_cast<const int*>(p + 16);
                a[mi][3] = *reinterpret_cast<const int*>(p + 8 * 80 + 16);
            }
#pragma unroll
            for (int ni = 0; ni < 4; ni++) {
                const int8_t* p = Bb + (wn0 + ni * 8 + g) * 80 + ks * 32 + q * 4;
                b[ni][0] = *reinterpret_cast<const int*>(p);
                b[ni][1] = *reinterpret_cast<const int*>(p + 16);
            }
#pragma unroll
            for (int mi = 0; mi < 4; mi++)
#pragma unroll
                for (int ni = 0; ni < 4; ni++)
                    mma_s8(acc[mi][ni], a[mi], b[ni]);
        }
        __syncthreads();
    }

    // ---- epilogue: out = acc*sx*sw + yl ----
#pragma unroll
    for (int mi = 0; mi < 4; mi++) {
        int r0 = m0 + wm0 + mi * 16 + g;
        int r1 = r0 + 8;
        float sx0 = __ldg(g_sx + r0), sx1 = __ldg(g_sx + r1);
#pragma unroll
        for (int ni = 0; ni < 4; ni++) {
            int c0 = n0 + wn0 + ni * 8 + 2 * q;
            float2 sw2 = *reinterpret_cast<const float2*>(g_sw + c0);
            float2 yl0 = *reinterpret_cast<const float2*>(g_yl + (size_t)r0 * ODIM + c0);
            float2 yl1 = *reinterpret_cast<const float2*>(g_yl + (size_t)r1 * ODIM + c0);
            float2 o0, o1;
            o0.x = ((float)acc[mi][ni][0] * sx0) * sw2.x + yl0.x;
            o0.y = ((float)acc[mi][ni][1] * sx0) * sw2.y + yl0.y;
            o1.x = ((float)acc[mi][ni][2] * sx1) * sw2.x + yl1.x;
            o1.y = ((float)acc[mi][ni][3] * sx1) * sw2.y + yl1.y;
            *reinterpret_cast<float2*>(out + (size_t)r0 * ODIM + c0) = o0;
            *reinterpret_cast<float2*>(out + (size_t)r1 * ODIM + c0) = o1;
        }
    }
}

// ---------------- launch ----------------
extern "C" void kernel_launch(void* const* d_in, const int* in_sizes, int n_in,
                              void* d_out, int out_size) {
    const float* x    = (const float*)d_in[0];  // (4,320,64,64)
    const float* w    = (const float*)d_in[1];  // (384,2944)
    const float* pd   = (const float*)d_in[2];  // (2944,32)
    const float* pu   = (const float*)d_in[3];  // (32,384)
    const float* bias = (const float*)d_in[4];  // (384,)
    float* out = (float*)d_out;                 // (4,4096,384) fp32

    quant_w_kernel<<<48, 256>>>(w);
    im2col_partial_kernel<<<dim3(64, NCH_P), 256>>>(x, pd);
    reduce_kernel<<<(M_TOK * RANKD) / 256, 256>>>();
    lora_up_kernel<<<M_TOK / 8, 256>>>(pu, bias);
    quant_x_kernel<<<dim3(64, NCH_Q), 256>>>(x);
    mma_gemm_kernel<<<384, 256>>>(out);
}

// round 14
// speedup vs baseline: 4.5937x; 1.1235x over previous
#include <cuda_runtime.h>
#include <cstdint>

// Problem constants
#define M_TOK 16384     // 4 * 64 * 64 tokens
#define KDIM  2944      // padded in_features (2880 real + 64 zero)
#define KREAL 2880
#define ODIM  384
#define RANKD 32

#define CH_P  40        // channels per chunk in partial (amax+LoRA-down) kernel
#define NCH_P 8
#define CH_Q  32        // channels per chunk in quantize kernel
#define NCH_Q 10

#define NKC   (KDIM / 16)   // 184 k-chunks of 16 bytes
#define NST   (KDIM / 64)   // 46 GEMM k-stages of 64 bytes
#define STAGE_BYTES 10240   // 128 rows * 80B padded stride
#define NPIPE 4
#define SMEM_GEMM (2 * NPIPE * STAGE_BYTES)   // 81920 B dynamic

// ---------------- device scratch (no cudaMalloc allowed) ----------------
// qx layout: [k-chunk (184)][token (16384)] x 16 bytes  -> coalesced writes+reads
__device__ __align__(16) int8_t g_qx[(size_t)NKC * M_TOK * 16];   // 48 MB
__device__ __align__(16) int8_t g_qw[(size_t)ODIM * KDIM];        // 1.1 MB row-major
__device__ float g_sx[M_TOK];
__device__ float g_sw[ODIM];
__device__ __align__(16) float g_rp[NCH_P][M_TOK][RANKD];         // 16.8 MB
__device__ float g_amp[NCH_P][M_TOK];
__device__ __align__(16) float g_yl[(size_t)M_TOK * ODIM];        // 25 MB (lora+bias)

// ---------------- PTX helpers (baseline compute_103 only!) ----------------
__device__ __forceinline__ uint32_t smem_u32(const void* p) {
    uint32_t a;
    asm("{ .reg .u64 t; cvta.to.shared.u64 t, %1; cvt.u32.u64 %0, t; }"
        : "=r"(a) : "l"(p));
    return a;
}
__device__ __forceinline__ void cp16(uint32_t s, const void* g) {
    asm volatile("cp.async.cg.shared.global [%0], [%1], 16;" :: "r"(s), "l"(g));
}
#define CP_COMMIT() asm volatile("cp.async.commit_group;" ::: "memory")
#define CP_WAIT(n)  asm volatile("cp.async.wait_group %0;" :: "n"(n) : "memory")

__device__ __forceinline__ void mma_s8(int* c, const int* a, const int* b) {
    asm volatile(
        "mma.sync.aligned.m16n8k32.row.col.s32.s8.s8.s32 "
        "{%0,%1,%2,%3}, {%4,%5,%6,%7}, {%8,%9}, {%0,%1,%2,%3};"
        : "+r"(c[0]), "+r"(c[1]), "+r"(c[2]), "+r"(c[3])
        : "r"(a[0]), "r"(a[1]), "r"(a[2]), "r"(a[3]), "r"(b[0]), "r"(b[1]));
}

// ---------------- math helpers ----------------
__device__ __forceinline__ void fma2(unsigned long long& acc,
                                     unsigned long long a,
                                     unsigned long long b) {
    asm("fma.rn.f32x2 %0, %1, %2, %0;" : "+l"(acc) : "l"(a), "l"(b));
}
__device__ __forceinline__ void load9(const float* __restrict__ xc,
                                      int ho, int wo, float v[9]) {
#pragma unroll
    for (int i = 0; i < 3; i++) {
        int h = ho + i - 1;
        bool hok = ((unsigned)h < 64u);
#pragma unroll
        for (int j = 0; j < 3; j++) {
            int wc = wo + j - 1;
            v[i * 3 + j] = (hok && ((unsigned)wc < 64u))
                               ? __ldg(xc + h * 64 + wc) : 0.0f;
        }
    }
}

// ---------------- kernel 1: per-out-channel int4 weight quant ----------------
__global__ void __launch_bounds__(256) quant_w_kernel(const float* __restrict__ w) {
    int warp = (blockIdx.x * blockDim.x + threadIdx.x) >> 5;
    int lane = threadIdx.x & 31;
    if (warp >= ODIM) return;
    const float* row = w + (size_t)warp * KDIM;
    float amax = 0.0f;
    for (int k = lane; k < KDIM; k += 32) amax = fmaxf(amax, fabsf(row[k]));
#pragma unroll
    for (int off = 16; off; off >>= 1)
        amax = fmaxf(amax, __shfl_xor_sync(0xFFFFFFFFu, amax, off));
    float s = fmaxf(__fdiv_rn(amax, 7.0f), 1e-8f);
    if (lane == 0) g_sw[warp] = s;
    int8_t* q = g_qw + (size_t)warp * KDIM;
    for (int k = lane; k < KDIM; k += 32) {
        float t = __fdiv_rn(row[k], s);            // exact: matches jnp round ties
        float r = fminf(fmaxf(rintf(t), -8.0f), 7.0f);
        q[k] = (int8_t)(int)r;
    }
}

// ---------------- kernel 2a: partial amax + partial LoRA-down ----------------
__global__ void __launch_bounds__(256) im2col_partial_kernel(
    const float* __restrict__ x, const float* __restrict__ pd) {
    __shared__ float spd[CH_P * 9 * 32];            // 46080 B
    int chunk = blockIdx.y;
    int tid = threadIdx.x;

    const float4* src = reinterpret_cast<const float4*>(pd + (size_t)chunk * CH_P * 9 * 32);
    float4* dst = reinterpret_cast<float4*>(spd);
#pragma unroll 4
    for (int i = tid; i < CH_P * 9 * 8; i += 256) dst[i] = __ldg(src + i);
    __syncthreads();

    int t  = blockIdx.x * 256 + tid;
    int wo = t & 63, ho = (t >> 6) & 63, n = t >> 12;
    const float* xb = x + ((size_t)n * 320 + chunk * CH_P) * 4096;

    unsigned long long acc2[16];
#pragma unroll
    for (int q = 0; q < 16; q++) acc2[q] = 0ULL;
    float amax = 0.0f;

    for (int c = 0; c < CH_P; c++) {
        const float* xc = xb + (size_t)c * 4096;
        float v[9];
        load9(xc, ho, wo, v);
        const ulonglong2* base =
            reinterpret_cast<const ulonglong2*>(spd + c * 9 * 32);
#pragma unroll
        for (int tp = 0; tp < 9; tp++) {
            float val = v[tp];
            amax = fmaxf(amax, fabsf(val));
            unsigned vb = __float_as_uint(val);
            unsigned long long v2;
            asm("mov.b64 %0, {%1, %1};" : "=l"(v2) : "r"(vb));
            const ulonglong2* prow = base + tp * 8;
#pragma unroll
            for (int q = 0; q < 8; q++) {
                ulonglong2 p = prow[q];
                fma2(acc2[2 * q],     v2, p.x);
                fma2(acc2[2 * q + 1], v2, p.y);
            }
        }
    }

    g_amp[chunk][t] = amax;
    unsigned long long* rout =
        reinterpret_cast<unsigned long long*>(&g_rp[chunk][t][0]);
#pragma unroll
    for (int q = 0; q < 16; q++) rout[q] = acc2[q];
}

// ---------------- kernel 2b: fused reduce + scale + LoRA-up + bias ----------
// One warp per token: lane r sums partials, amax -> g_sx, then yl = r.PU + bias.
__global__ void __launch_bounds__(256) reduce_lora_kernel(
    const float* __restrict__ pu, const float* __restrict__ bias) {
    __shared__ float sPU[RANKD * ODIM];             // 49152 B
    int tid = threadIdx.x, wid = tid >> 5, lane = tid & 31;
#pragma unroll 4
    for (int i = tid; i < RANKD * ODIM / 4; i += 256)
        reinterpret_cast<float4*>(sPU)[i] =
            __ldg(reinterpret_cast<const float4*>(pu) + i);
    __syncthreads();

    int t = blockIdx.x * 8 + wid;

    // rank-sum over the 8 channel-chunk partials
    float rsum = 0.0f;
#pragma unroll
    for (int ch = 0; ch < NCH_P; ch++) rsum += g_rp[ch][t][lane];

    // amax over chunks -> per-token scale
    float am = (lane < NCH_P) ? g_amp[lane][t] : 0.0f;
#pragma unroll
    for (int off = 4; off; off >>= 1)
        am = fmaxf(am, __shfl_xor_sync(0xFFFFFFFFu, am, off));
    if (lane == 0)
        g_sx[t] = fmaxf(__fdiv_rn(am, 7.0f), 1e-8f);

    float acc[12];
#pragma unroll
    for (int j = 0; j < 12; j++) acc[j] = __ldg(bias + lane + 32 * j);
#pragma unroll
    for (int r = 0; r < RANKD; r++) {
        float rb = __shfl_sync(0xFFFFFFFFu, rsum, r);
        const float* prow = sPU + r * ODIM + lane;
#pragma unroll
        for (int j = 0; j < 12; j++) acc[j] = fmaf(rb, prow[32 * j], acc[j]);
    }
    float* yrow = g_yl + (size_t)t * ODIM + lane;
#pragma unroll
    for (int j = 0; j < 12; j++) yrow[32 * j] = acc[j];
}

// ---------------- kernel 2c: quantize + pack int8 (magic-FMA round) ----------
// round-half-even(v*rs) lands in the low mantissa byte of fmaf(v,rs,1.5*2^23).
// |v/s| <= 7 by construction, so the [-8,7] clamp is a provable no-op.
__global__ void __launch_bounds__(256) quant_x_kernel(const float* __restrict__ x) {
    int chunk = blockIdx.y;
    int tid = threadIdx.x;
    int t  = blockIdx.x * 256 + tid;
    int wo = t & 63, ho = (t >> 6) & 63, n = t >> 12;
    float rs = __fdiv_rn(1.0f, g_sx[t]);
    const float magic = 12582912.0f;                // 1.5 * 2^23
    const float* xb = x + ((size_t)n * 320 + chunk * CH_Q) * 4096;

#pragma unroll
    for (int grp = 0; grp < 2; grp++) {            // 16 channels -> 144 B -> 9 chunks
        unsigned hw[36];
#pragma unroll
        for (int i = 0; i < 36; i++) hw[i] = 0u;
#pragma unroll
        for (int c16 = 0; c16 < 16; c16++) {
            const float* xc = xb + (size_t)(grp * 16 + c16) * 4096;
            float v[9];
            load9(xc, ho, wo, v);
#pragma unroll
            for (int tp = 0; tp < 9; tp++) {
                unsigned u = __float_as_uint(fmaf(v[tp], rs, magic));
                int idx = c16 * 9 + tp;
                hw[idx >> 2] |= (u & 0xFFu) << ((idx & 3) * 8);
            }
        }
        int kc0 = chunk * 18 + grp * 9;
#pragma unroll
        for (int j = 0; j < 9; j++) {
            uint4 w4 = make_uint4(hw[4 * j], hw[4 * j + 1], hw[4 * j + 2], hw[4 * j + 3]);
            *reinterpret_cast<uint4*>(
                g_qx + ((size_t)(kc0 + j) * M_TOK + t) * 16) = w4;
        }
    }
    // zero pad chunks 180..183 (k bytes 2880..2944)
    if (chunk == NCH_Q - 1) {
        uint4 z = make_uint4(0, 0, 0, 0);
#pragma unroll
        for (int kc = 180; kc < 184; kc++)
            *reinterpret_cast<uint4*>(g_qx + ((size_t)kc * M_TOK + t) * 16) = z;
    }
}

// ---------------- kernel 3: IMMA GEMM, 4-stage cp.async + epilogue ----------
// Block 128x128, 8 warps in 2(m)x4(n), warp tile 64x32. k-stage = 64 bytes,
// 4-deep cp.async pipeline. smem row stride 80B -> conflict-free fragment LDS.
__global__ void __launch_bounds__(256, 2) mma_gemm_kernel(float* __restrict__ out) {
    extern __shared__ int8_t dsm[];
    int8_t* sA = dsm;                              // NPIPE * STAGE_BYTES
    int8_t* sB = dsm + NPIPE * STAGE_BYTES;

    int tid = threadIdx.x, wid = tid >> 5, lane = tid & 31;
    int g = lane >> 2, q = lane & 3;
    int mt = blockIdx.x / 3, nt = blockIdx.x - mt * 3;
    int m0 = mt << 7, n0 = nt << 7;
    int wm0 = (wid >> 2) << 6;      // 0 or 64
    int wn0 = (wid & 3) << 5;       // 0,32,64,96

    uint32_t sAb = smem_u32(sA), sBb = smem_u32(sB);

    auto issue = [&](int st, int kt) {
#pragma unroll
        for (int rep = 0; rep < 2; rep++) {
            int c = tid + (rep << 8);
            int seg = c >> 7, row = c & 127;
            cp16(sAb + st * STAGE_BYTES + row * 80 + seg * 16,
                 g_qx + ((size_t)(kt * 4 + seg) * M_TOK + m0 + row) * 16);
            cp16(sBb + st * STAGE_BYTES + row * 80 + seg * 16,
                 g_qw + (size_t)(n0 + row) * KDIM + kt * 64 + seg * 16);
        }
        CP_COMMIT();
    };

    int acc[4][4][4];
#pragma unroll
    for (int mi = 0; mi < 4; mi++)
#pragma unroll
        for (int ni = 0; ni < 4; ni++)
#pragma unroll
            for (int r = 0; r < 4; r++) acc[mi][ni][r] = 0;

    issue(0, 0); issue(1, 1); issue(2, 2);

    for (int kt = 0; kt < NST; kt++) {
        int st = kt & (NPIPE - 1);
        if (kt < NST - 2)      CP_WAIT(2);
        else if (kt == NST - 2) CP_WAIT(1);
        else                    CP_WAIT(0);
        __syncthreads();

        const int8_t* Ab = sA + st * STAGE_BYTES;
        const int8_t* Bb = sB + st * STAGE_BYTES;
#pragma unroll
        for (int ks = 0; ks < 2; ks++) {
            int a[4][4], b[4][2];
#pragma unroll
            for (int mi = 0; mi < 4; mi++) {
                const int8_t* p = Ab + (wm0 + mi * 16 + g) * 80 + ks * 32 + q * 4;
                a[mi][0] = *reinterpret_cast<const int*>(p);
                a[mi][1] = *reinterpret_cast<const int*>(p + 8 * 80);
                a[mi][2] = *reinterpret_cast<const int*>(p + 16);
                a[mi][3] = *reinterpret_cast<const int*>(p + 8 * 80 + 16);
            }
#pragma unroll
            for (int ni = 0; ni < 4; ni++) {
                const int8_t* p = Bb + (wn0 + ni * 8 + g) * 80 + ks * 32 + q * 4;
                b[ni][0] = *reinterpret_cast<const int*>(p);
                b[ni][1] = *reinterpret_cast<const int*>(p + 16);
            }
#pragma unroll
            for (int mi = 0; mi < 4; mi++)
#pragma unroll
                for (int ni = 0; ni < 4; ni++)
                    mma_s8(acc[mi][ni], a[mi], b[ni]);
        }
        __syncthreads();
        int nk = kt + 3;
        if (nk < NST) issue(nk & (NPIPE - 1), nk);
    }

    // ---- epilogue: out = acc*sx*sw + yl ----
#pragma unroll
    for (int mi = 0; mi < 4; mi++) {
        int r0 = m0 + wm0 + mi * 16 + g;
        int r1 = r0 + 8;
        float sx0 = __ldg(g_sx + r0), sx1 = __ldg(g_sx + r1);
#pragma unroll
        for (int ni = 0; ni < 4; ni++) {
            int c0 = n0 + wn0 + ni * 8 + 2 * q;
            float2 sw2 = *reinterpret_cast<const float2*>(g_sw + c0);
            float2 yl0 = *reinterpret_cast<const float2*>(g_yl + (size_t)r0 * ODIM + c0);
            float2 yl1 = *reinterpret_cast<const float2*>(g_yl + (size_t)r1 * ODIM + c0);
            float2 o0, o1;
            o0.x = ((float)acc[mi][ni][0] * sx0) * sw2.x + yl0.x;
            o0.y = ((float)acc[mi][ni][1] * sx0) * sw2.y + yl0.y;
            o1.x = ((float)acc[mi][ni][2] * sx1) * sw2.x + yl1.x;
            o1.y = ((float)acc[mi][ni][3] * sx1) * sw2.y + yl1.y;
            *reinterpret_cast<float2*>(out + (size_t)r0 * ODIM + c0) = o0;
            *reinterpret_cast<float2*>(out + (size_t)r1 * ODIM + c0) = o1;
        }
    }
}

// ---------------- launch ----------------
extern "C" void kernel_launch(void* const* d_in, const int* in_sizes, int n_in,
                              void* d_out, int out_size) {
    const float* x    = (const float*)d_in[0];  // (4,320,64,64)
    const float* w    = (const float*)d_in[1];  // (384,2944)
    const float* pd   = (const float*)d_in[2];  // (2944,32)
    const float* pu   = (const float*)d_in[3];  // (32,384)
    const float* bias = (const float*)d_in[4];  // (384,)
    float* out = (float*)d_out;                 // (4,4096,384) fp32

    static bool attr_set = false;
    if (!attr_set) {
        cudaFuncSetAttribute(mma_gemm_kernel,
                             cudaFuncAttributeMaxDynamicSharedMemorySize, SMEM_GEMM);
        attr_set = true;
    }

    quant_w_kernel<<<48, 256>>>(w);
    im2col_partial_kernel<<<dim3(64, NCH_P), 256>>>(x, pd);
    reduce_lora_kernel<<<M_TOK / 8, 256>>>(pu, bias);
    quant_x_kernel<<<dim3(64, NCH_Q), 256>>>(x);
    mma_gemm_kernel<<<384, 256, SMEM_GEMM>>>(out);
}